// round 3
// baseline (speedup 1.0000x reference)
// FlashSparseAttention — round 1: all-fp32 correct baseline.
// B=2, S=2048, H=2048, NH=16, NKV=4, HD=128, GQA groups=4, RoPE theta=1e4.
// Pipeline: 3x SGEMM (QKV) -> RoPE -> fp32 flash attention (causal) -> SGEMM (O).
#include <cuda_runtime.h>
#include <math.h>

#define B_    2
#define S_    2048
#define H_    2048
#define NH_   16
#define NKV_  4
#define HD_   128
#define M_    (B_*S_)      // 4096 rows

// ---------------- scratch (device globals: allocation-free) ----------------
__device__ float g_q [(size_t)M_*NH_*HD_];    // 32 MB
__device__ float g_k [(size_t)M_*NKV_*HD_];   // 8 MB
__device__ float g_v [(size_t)M_*NKV_*HD_];   // 8 MB
__device__ float g_ao[(size_t)M_*NH_*HD_];    // 32 MB
__device__ float g_cos[S_*64];
__device__ float g_sin[S_*64];

// ---------------- SGEMM: C[M,N] = A[M,K] * W[N,K]^T  (both row-major) ------
// 128x128 block tile, BK=8, 256 threads, 8x8 per-thread.
// a_sel: 0 -> use A param, 1 -> g_ao.   c_sel: 0 -> C param, 1/2/3 -> g_q/g_k/g_v.
__global__ __launch_bounds__(256) void gemm_nt(
    const float* Ap_, const float* __restrict__ W, float* Cp_,
    int M, int N, int K, int a_sel, int c_sel)
{
    const float* A = (a_sel == 1) ? (const float*)g_ao : Ap_;
    float* C = Cp_;
    if (c_sel == 1) C = g_q; else if (c_sel == 2) C = g_k; else if (c_sel == 3) C = g_v;

    __shared__ float As[8][128];
    __shared__ float Ws[8][128];

    const int tid = threadIdx.x;
    const int tx = tid & 15, ty = tid >> 4;
    const int m0 = blockIdx.y * 128, n0 = blockIdx.x * 128;
    const int lr = tid >> 1;            // 0..127
    const int lc = (tid & 1) * 4;       // 0 or 4

    const float* Ald = A + (size_t)(m0 + lr) * K + lc;
    const float* Wld = W + (size_t)(n0 + lr) * K + lc;

    float acc[8][8];
#pragma unroll
    for (int i = 0; i < 8; i++)
#pragma unroll
        for (int j = 0; j < 8; j++) acc[i][j] = 0.f;

    for (int k0 = 0; k0 < K; k0 += 8) {
        float4 a4 = *(const float4*)(Ald + k0);
        float4 w4 = *(const float4*)(Wld + k0);
        As[lc + 0][lr] = a4.x; As[lc + 1][lr] = a4.y;
        As[lc + 2][lr] = a4.z; As[lc + 3][lr] = a4.w;
        Ws[lc + 0][lr] = w4.x; Ws[lc + 1][lr] = w4.y;
        Ws[lc + 2][lr] = w4.z; Ws[lc + 3][lr] = w4.w;
        __syncthreads();
#pragma unroll
        for (int kk = 0; kk < 8; kk++) {
            float ra[8], rb[8];
            *(float4*)&ra[0] = *(const float4*)&As[kk][ty * 8];
            *(float4*)&ra[4] = *(const float4*)&As[kk][ty * 8 + 4];
            *(float4*)&rb[0] = *(const float4*)&Ws[kk][tx * 8];
            *(float4*)&rb[4] = *(const float4*)&Ws[kk][tx * 8 + 4];
#pragma unroll
            for (int i = 0; i < 8; i++)
#pragma unroll
                for (int j = 0; j < 8; j++)
                    acc[i][j] = fmaf(ra[i], rb[j], acc[i][j]);
        }
        __syncthreads();
    }

#pragma unroll
    for (int i = 0; i < 8; i++) {
        float* cp = C + (size_t)(m0 + ty * 8 + i) * N + n0 + tx * 8;
        float4 o0 = make_float4(acc[i][0], acc[i][1], acc[i][2], acc[i][3]);
        float4 o1 = make_float4(acc[i][4], acc[i][5], acc[i][6], acc[i][7]);
        *(float4*)cp = o0;
        *(float4*)(cp + 4) = o1;
    }
}

// ---------------- RoPE table (double precision trig) ------------------------
__global__ void rope_table_kernel()
{
    int idx = blockIdx.x * blockDim.x + threadIdx.x;
    if (idx >= S_ * 64) return;
    int s = idx >> 6, i = idx & 63;
    double inv = pow(10000.0, -(double)(2 * i) / 128.0);
    double f = (double)s * inv;
    g_cos[idx] = (float)cos(f);
    g_sin[idx] = (float)sin(f);
}

// ---------------- RoPE apply (in place on g_q or g_k) -----------------------
__global__ void rope_apply(int which, int nheads, int total)
{
    int idx = blockIdx.x * blockDim.x + threadIdx.x;
    if (idx >= total) return;
    float* x = (which == 1) ? g_q : g_k;
    int i = idx & 63;
    int h = (idx >> 6) % nheads;
    int m = idx / (64 * nheads);
    int s = m & (S_ - 1);
    float c  = g_cos[s * 64 + i];
    float sn = g_sin[s * 64 + i];
    float* p = x + ((size_t)m * nheads + h) * HD_;
    float x1 = p[i], x2 = p[i + 64];
    p[i]      = x1 * c - x2 * sn;
    p[i + 64] = x2 * c + x1 * sn;
}

// ---------------- fp32 causal flash attention -------------------------------
// Grid: (S/64, NH, B). 256 threads as 16x16. Per thread: 4 q-rows x (4 S-cols / 8 O-cols).
#define BR 64
#define BC 64
#define QSTR 132   // 128 + 4 pad (keeps float4 alignment, kills bank conflicts)
#define PSTR 68
#define FLASH_SMEM ((2*BR*QSTR + BR*PSTR) * (int)sizeof(float))   // 84992 B

__global__ __launch_bounds__(256, 2) void flash_attn()
{
    extern __shared__ float sm[];
    float* Qs = sm;                   // [64][132]
    float* Ks = sm + BR * QSTR;       // [64][132], reused for V
    float* Ps = sm + 2 * BR * QSTR;   // [64][68]

    const int tid = threadIdx.x;
    const int tx = tid & 15, ty = tid >> 4;
    const int qb = blockIdx.x, h = blockIdx.y, b = blockIdx.z;
    const int hk = h >> 2;            // GQA: 4 q-heads per kv-head
    const int q0 = qb * BR;

    // load Q tile [64][128] -> padded smem
    const float* Qg = g_q + (((size_t)b * S_ + q0) * NH_ + h) * HD_;
#pragma unroll 4
    for (int idx = tid; idx < BR * 32; idx += 256) {
        int r = idx >> 5, c4 = idx & 31;
        *(float4*)&Qs[r * QSTR + c4 * 4] =
            *(const float4*)(Qg + (size_t)r * (NH_ * HD_) + c4 * 4);
    }

    float m_i[4], l_i[4], acc[4][8];
#pragma unroll
    for (int i = 0; i < 4; i++) {
        m_i[i] = -INFINITY; l_i[i] = 0.f;
#pragma unroll
        for (int c = 0; c < 8; c++) acc[i][c] = 0.f;
    }

    const float scale = 0.08838834764831845f;   // 1/sqrt(128)

    for (int jb = 0; jb <= qb; jb++) {
        const int j0 = jb * BC;

        // load K tile
        const float* Kg = g_k + (((size_t)b * S_ + j0) * NKV_ + hk) * HD_;
#pragma unroll 4
        for (int idx = tid; idx < BC * 32; idx += 256) {
            int r = idx >> 5, c4 = idx & 31;
            *(float4*)&Ks[r * QSTR + c4 * 4] =
                *(const float4*)(Kg + (size_t)r * (NKV_ * HD_) + c4 * 4);
        }
        __syncthreads();

        // S = Q K^T : thread owns rows ty*4+i, cols tx + 16*jj
        float sv[4][4];
#pragma unroll
        for (int i = 0; i < 4; i++)
#pragma unroll
            for (int jj = 0; jj < 4; jj++) sv[i][jj] = 0.f;

        for (int d4 = 0; d4 < 32; d4++) {
            float4 qv[4], kvv[4];
#pragma unroll
            for (int i = 0; i < 4; i++)
                qv[i] = *(const float4*)&Qs[(ty * 4 + i) * QSTR + d4 * 4];
#pragma unroll
            for (int jj = 0; jj < 4; jj++)
                kvv[jj] = *(const float4*)&Ks[(tx + 16 * jj) * QSTR + d4 * 4];
#pragma unroll
            for (int i = 0; i < 4; i++)
#pragma unroll
                for (int jj = 0; jj < 4; jj++) {
                    sv[i][jj] = fmaf(qv[i].x, kvv[jj].x, sv[i][jj]);
                    sv[i][jj] = fmaf(qv[i].y, kvv[jj].y, sv[i][jj]);
                    sv[i][jj] = fmaf(qv[i].z, kvv[jj].z, sv[i][jj]);
                    sv[i][jj] = fmaf(qv[i].w, kvv[jj].w, sv[i][jj]);
                }
        }

        const bool diag = (jb == qb);
#pragma unroll
        for (int i = 0; i < 4; i++) {
            const int row = q0 + ty * 4 + i;
            float mx = -INFINITY;
#pragma unroll
            for (int jj = 0; jj < 4; jj++) {
                float x = sv[i][jj] * scale;
                if (diag && (j0 + tx + 16 * jj) > row) x = -INFINITY;
                sv[i][jj] = x;
                mx = fmaxf(mx, x);
            }
            // row reduce over the 16 tx lanes (lanes 0-15 / 16-31 are separate ty)
#pragma unroll
            for (int off = 8; off; off >>= 1)
                mx = fmaxf(mx, __shfl_xor_sync(0xffffffffu, mx, off));
            float mnew = fmaxf(m_i[i], mx);
            float corr = __expf(m_i[i] - mnew);
            float rs = 0.f;
#pragma unroll
            for (int jj = 0; jj < 4; jj++) {
                float p = __expf(sv[i][jj] - mnew);
                sv[i][jj] = p;
                rs += p;
            }
#pragma unroll
            for (int off = 8; off; off >>= 1)
                rs += __shfl_xor_sync(0xffffffffu, rs, off);
            l_i[i] = l_i[i] * corr + rs;
            m_i[i] = mnew;
#pragma unroll
            for (int c = 0; c < 8; c++) acc[i][c] *= corr;
#pragma unroll
            for (int jj = 0; jj < 4; jj++)
                Ps[(ty * 4 + i) * PSTR + tx + 16 * jj] = sv[i][jj];
        }
        __syncthreads();   // P visible; K reads done -> safe to overwrite with V

        // load V tile into K buffer
        const float* Vg = g_v + (((size_t)b * S_ + j0) * NKV_ + hk) * HD_;
#pragma unroll 4
        for (int idx = tid; idx < BC * 32; idx += 256) {
            int r = idx >> 5, c4 = idx & 31;
            *(float4*)&Ks[r * QSTR + c4 * 4] =
                *(const float4*)(Vg + (size_t)r * (NKV_ * HD_) + c4 * 4);
        }
        __syncthreads();

        // O += P V : thread owns rows ty*4+i, cols tx*8..tx*8+7
#pragma unroll 4
        for (int j = 0; j < BC; j++) {
            float pv[4];
#pragma unroll
            for (int i = 0; i < 4; i++) pv[i] = Ps[(ty * 4 + i) * PSTR + j];
            float4 v0 = *(const float4*)&Ks[j * QSTR + tx * 8];
            float4 v1 = *(const float4*)&Ks[j * QSTR + tx * 8 + 4];
            float vv[8] = {v0.x, v0.y, v0.z, v0.w, v1.x, v1.y, v1.z, v1.w};
#pragma unroll
            for (int i = 0; i < 4; i++)
#pragma unroll
                for (int c = 0; c < 8; c++)
                    acc[i][c] = fmaf(pv[i], vv[c], acc[i][c]);
        }
        __syncthreads();   // V reads done -> next iteration may overwrite
    }

    // write O / l
#pragma unroll
    for (int i = 0; i < 4; i++) {
        float inv = 1.0f / l_i[i];
        float* Og = g_ao + (((size_t)b * S_ + q0 + ty * 4 + i) * NH_ + h) * HD_ + tx * 8;
        float4 o0 = make_float4(acc[i][0] * inv, acc[i][1] * inv, acc[i][2] * inv, acc[i][3] * inv);
        float4 o1 = make_float4(acc[i][4] * inv, acc[i][5] * inv, acc[i][6] * inv, acc[i][7] * inv);
        *(float4*)Og = o0;
        *(float4*)(Og + 4) = o1;
    }
}

// ---------------- launch ----------------------------------------------------
extern "C" void kernel_launch(void* const* d_in, const int* in_sizes, int n_in,
                              void* d_out, int out_size)
{
    (void)in_sizes; (void)n_in; (void)out_size;
    const float* hs = (const float*)d_in[0];
    const float* Wq = (const float*)d_in[1];
    const float* Wk = (const float*)d_in[2];
    const float* Wv = (const float*)d_in[3];
    const float* Wo = (const float*)d_in[4];
    float* out = (float*)d_out;

    rope_table_kernel<<<(S_ * 64 + 255) / 256, 256>>>();

    // QKV projections
    gemm_nt<<<dim3((NH_ * HD_) / 128, M_ / 128), 256>>>(hs, Wq, nullptr, M_, NH_ * HD_, H_, 0, 1);
    gemm_nt<<<dim3((NKV_ * HD_) / 128, M_ / 128), 256>>>(hs, Wk, nullptr, M_, NKV_ * HD_, H_, 0, 2);
    gemm_nt<<<dim3((NKV_ * HD_) / 128, M_ / 128), 256>>>(hs, Wv, nullptr, M_, NKV_ * HD_, H_, 0, 3);

    // RoPE
    int tq = M_ * NH_ * 64;
    rope_apply<<<(tq + 255) / 256, 256>>>(1, NH_, tq);
    int tk = M_ * NKV_ * 64;
    rope_apply<<<(tk + 255) / 256, 256>>>(2, NKV_, tk);

    // Flash attention
    cudaFuncSetAttribute(flash_attn, cudaFuncAttributeMaxDynamicSharedMemorySize, FLASH_SMEM);
    flash_attn<<<dim3(S_ / BR, NH_, B_), 256, FLASH_SMEM>>>();

    // Output projection
    gemm_nt<<<dim3(H_ / 128, M_ / 128), 256>>>(nullptr, Wo, out, M_, H_, H_, 1, 0);
}

// round 6
// speedup vs baseline: 1.7615x; 1.7615x over previous
// FlashSparseAttention — round 5: mma.sync bf16x3 split GEMMs (B-fragment pairing FIXED)
// + fp32 SIMT flash attention.
// B=2, S=2048, H=2048, NH=16, NKV=4, HD=128, GQA groups=4, RoPE theta=1e4.
#include <cuda_runtime.h>
#include <cuda_bf16.h>
#include <math.h>
#include <stdint.h>

#define B_    2
#define S_    2048
#define H_    2048
#define NH_   16
#define NKV_  4
#define HD_   128
#define M_    (B_*S_)      // 4096 rows

// ---------------- scratch (device globals: allocation-free) ----------------
__device__ float g_q [(size_t)M_*NH_*HD_];    // 32 MB
__device__ float g_k [(size_t)M_*NKV_*HD_];   // 8 MB
__device__ float g_v [(size_t)M_*NKV_*HD_];   // 8 MB
__device__ float g_ao[(size_t)M_*NH_*HD_];    // 32 MB
__device__ float g_cos[S_*64];
__device__ float g_sin[S_*64];

// bf16 hi/lo splits
__device__ __nv_bfloat16 g_ah [(size_t)M_*H_],   g_al [(size_t)M_*H_];
__device__ __nv_bfloat16 g_wqh[(size_t)2048*H_], g_wql[(size_t)2048*H_];
__device__ __nv_bfloat16 g_wkh[(size_t)512*H_],  g_wkl[(size_t)512*H_];
__device__ __nv_bfloat16 g_wvh[(size_t)512*H_],  g_wvl[(size_t)512*H_];
__device__ __nv_bfloat16 g_woh[(size_t)2048*H_], g_wol[(size_t)2048*H_];
__device__ __nv_bfloat16 g_aoh[(size_t)M_*2048], g_aol[(size_t)M_*2048];

// ---------------- PTX helpers ------------------------------------------------
__device__ __forceinline__ uint32_t smem_u32(const void* p) {
    uint32_t a;
    asm("{ .reg .u64 t; cvta.to.shared.u64 t, %1; cvt.u32.u64 %0, t; }" : "=r"(a) : "l"(p));
    return a;
}
#define CP_ASYNC16(dst, src) \
    asm volatile("cp.async.cg.shared.global [%0], [%1], 16;" :: "r"(dst), "l"(src) : "memory")
#define CP_COMMIT()  asm volatile("cp.async.commit_group;" ::: "memory")
#define CP_WAIT1()   asm volatile("cp.async.wait_group 1;" ::: "memory")
#define CP_WAIT0()   asm volatile("cp.async.wait_group 0;" ::: "memory")

#define LDSM_X4(r0, r1, r2, r3, addr) \
    asm volatile("ldmatrix.sync.aligned.m8n8.x4.shared.b16 {%0,%1,%2,%3}, [%4];" \
        : "=r"(r0), "=r"(r1), "=r"(r2), "=r"(r3) : "r"(addr))

#define MMA_BF16(d, a, b0, b1) \
    asm volatile("mma.sync.aligned.m16n8k16.row.col.f32.bf16.bf16.f32 " \
        "{%0,%1,%2,%3}, {%4,%5,%6,%7}, {%8,%9}, {%0,%1,%2,%3};" \
        : "+f"((d)[0]), "+f"((d)[1]), "+f"((d)[2]), "+f"((d)[3]) \
        : "r"((a)[0]), "r"((a)[1]), "r"((a)[2]), "r"((a)[3]), "r"(b0), "r"(b1))

// ---------------- bf16 split kernel -----------------------------------------
__device__ __forceinline__ void split1(float x, __nv_bfloat16& h, __nv_bfloat16& l) {
    h = __float2bfloat16(x);
    l = __float2bfloat16(x - __bfloat162float(h));
}
__global__ void split_bf16(const float* __restrict__ srcp, int sel, int n)
{
    int i = (blockIdx.x * blockDim.x + threadIdx.x) * 4;
    if (i >= n) return;
    const float* src; __nv_bfloat16 *hi, *lo;
    switch (sel) {
        case 0: src = srcp; hi = g_ah;  lo = g_al;  break;
        case 1: src = srcp; hi = g_wqh; lo = g_wql; break;
        case 2: src = srcp; hi = g_wkh; lo = g_wkl; break;
        case 3: src = srcp; hi = g_wvh; lo = g_wvl; break;
        case 4: src = srcp; hi = g_woh; lo = g_wol; break;
        default: src = g_ao; hi = g_aoh; lo = g_aol; break;
    }
    float4 v = *(const float4*)(src + i);
    __nv_bfloat16 h0, l0, h1, l1, h2, l2, h3, l3;
    split1(v.x, h0, l0); split1(v.y, h1, l1);
    split1(v.z, h2, l2); split1(v.w, h3, l3);
    *(__nv_bfloat162*)(hi + i)     = __nv_bfloat162(h0, h1);
    *(__nv_bfloat162*)(hi + i + 2) = __nv_bfloat162(h2, h3);
    *(__nv_bfloat162*)(lo + i)     = __nv_bfloat162(l0, l1);
    *(__nv_bfloat162*)(lo + i + 2) = __nv_bfloat162(l2, l3);
}

// ---------------- mma.sync bf16x3 GEMM ---------------------------------------
// C[M,N] = A[M,K] * W[N,K]^T with A = Ah+Al, W = Bh+Bl (drop Al*Bl term).
// CTA tile 128x128, BK=32, 256 thr (8 warps, 2x4), warp tile 64x32.
// Smem stage: Ah|Al|Bh|Bl, each 128 rows x 64B (32 bf16), chunk-swizzled.
#define BKK       32
#define NKI       (H_/BKK)          // 64 k-iterations
#define TILE8K    8192              // one 128x32 bf16 tile
#define STAGE_B   (4*TILE8K)        // 32 KB
#define GEMM_SMEM (2*STAGE_B)       // 64 KB

__device__ __forceinline__ uint32_t sw_off(int row, int chunk) {
    return (uint32_t)(row * 64 + ((chunk ^ ((row >> 1) & 3)) << 4));
}

__global__ __launch_bounds__(256) void tc_gemm(int which, float* Cout)
{
    extern __shared__ char smem[];
    const uint32_t sb0 = smem_u32(smem);
    const int tid = threadIdx.x;
    const int wid = tid >> 5, lane = tid & 31;
    const int wm = wid >> 2, wn = wid & 3;        // 2 x 4 warp grid

    const __nv_bfloat16 *Ah, *Al, *Bh, *Bl;
    float* C; int N;
    switch (which) {
        case 0: Ah = g_ah;  Al = g_al;  Bh = g_wqh; Bl = g_wql; C = g_q;  N = 2048; break;
        case 1: Ah = g_ah;  Al = g_al;  Bh = g_wkh; Bl = g_wkl; C = g_k;  N = 512;  break;
        case 2: Ah = g_ah;  Al = g_al;  Bh = g_wvh; Bl = g_wvl; C = g_v;  N = 512;  break;
        default: Ah = g_aoh; Al = g_aol; Bh = g_woh; Bl = g_wol; C = Cout; N = 2048; break;
    }
    const int m0 = blockIdx.y * 128, n0 = blockIdx.x * 128;

    const __nv_bfloat16* bases[4];
    bases[0] = Ah + (size_t)m0 * H_;
    bases[1] = Al + (size_t)m0 * H_;
    bases[2] = Bh + (size_t)n0 * H_;
    bases[3] = Bl + (size_t)n0 * H_;

    auto load_stage = [&](int kt, int s) {
        const int k0 = kt * BKK;
        const uint32_t stage = sb0 + s * STAGE_B;
#pragma unroll
        for (int i = 0; i < 8; ++i) {
            int ch = tid + (i << 8);
            int t = ch >> 9, w = ch & 511;
            int r = w >> 2, c = w & 3;
            const __nv_bfloat16* src = bases[t] + (size_t)r * H_ + k0 + c * 8;
            uint32_t dst = stage + t * TILE8K + sw_off(r, c);
            CP_ASYNC16(dst, src);
        }
        CP_COMMIT();
    };

    float acc[4][4][4];
#pragma unroll
    for (int mi = 0; mi < 4; mi++)
#pragma unroll
        for (int ni = 0; ni < 4; ni++)
#pragma unroll
            for (int e = 0; e < 4; e++) acc[mi][ni][e] = 0.f;

    load_stage(0, 0);

    for (int kt = 0; kt < NKI; ++kt) {
        if (kt + 1 < NKI) { load_stage(kt + 1, (kt + 1) & 1); CP_WAIT1(); }
        else              { CP_WAIT0(); }
        __syncthreads();

        const uint32_t stage = sb0 + (kt & 1) * STAGE_B;
        const int lrow = lane & 15;
        const int lchunk = lane >> 4;

#pragma unroll
        for (int kk = 0; kk < 2; ++kk) {
            const int cc = kk * 2 + lchunk;
            uint32_t AHf[4][4], ALf[4][4];
#pragma unroll
            for (int mi = 0; mi < 4; ++mi) {
                int row = wm * 64 + mi * 16 + lrow;
                uint32_t a = stage + sw_off(row, cc);
                LDSM_X4(AHf[mi][0], AHf[mi][1], AHf[mi][2], AHf[mi][3], a);
                LDSM_X4(ALf[mi][0], ALf[mi][1], ALf[mi][2], ALf[mi][3], a + TILE8K);
            }
            uint32_t BHf[2][4], BLf[2][4];
#pragma unroll
            for (int g = 0; g < 2; ++g) {
                int row = wn * 32 + g * 16 + lrow;
                uint32_t a = stage + 2 * TILE8K + sw_off(row, cc);
                LDSM_X4(BHf[g][0], BHf[g][1], BHf[g][2], BHf[g][3], a);
                LDSM_X4(BLf[g][0], BLf[g][1], BLf[g][2], BLf[g][3], a + TILE8K);
            }
            // ldmatrix reg order: r0 = n0-7 k-lo, r1 = n8-15 k-lo, r2 = n0-7 k-hi,
            // r3 = n8-15 k-hi.  mma B fragment = (k-lo, k-hi) for SAME n-block:
            //   n-block 0 -> (r0, r2),  n-block 1 -> (r1, r3).
#pragma unroll
            for (int mi = 0; mi < 4; ++mi)
#pragma unroll
                for (int ni = 0; ni < 4; ++ni) {
                    const int g = ni >> 1, sub = ni & 1;
                    MMA_BF16(acc[mi][ni], AHf[mi], BHf[g][sub], BHf[g][sub + 2]);
                    MMA_BF16(acc[mi][ni], AHf[mi], BLf[g][sub], BLf[g][sub + 2]);
                    MMA_BF16(acc[mi][ni], ALf[mi], BHf[g][sub], BHf[g][sub + 2]);
                }
        }
        __syncthreads();
    }

    // epilogue: acc[mi][ni]: d0,d1 -> (row lane/4, col 2(lane%4)+{0,1}); d2,d3 -> row+8
#pragma unroll
    for (int mi = 0; mi < 4; ++mi) {
        const int row = m0 + wm * 64 + mi * 16 + (lane >> 2);
#pragma unroll
        for (int ni = 0; ni < 4; ++ni) {
            const int col = n0 + wn * 32 + ni * 8 + (lane & 3) * 2;
            float* cp = C + (size_t)row * N + col;
            *(float2*)cp = make_float2(acc[mi][ni][0], acc[mi][ni][1]);
            *(float2*)(cp + (size_t)8 * N) = make_float2(acc[mi][ni][2], acc[mi][ni][3]);
        }
    }
}

// ---------------- RoPE table (double precision trig) ------------------------
__global__ void rope_table_kernel()
{
    int idx = blockIdx.x * blockDim.x + threadIdx.x;
    if (idx >= S_ * 64) return;
    int s = idx >> 6, i = idx & 63;
    double inv = pow(10000.0, -(double)(2 * i) / 128.0);
    double f = (double)s * inv;
    g_cos[idx] = (float)cos(f);
    g_sin[idx] = (float)sin(f);
}

// ---------------- RoPE apply (in place on g_q or g_k) -----------------------
__global__ void rope_apply(int which, int nheads, int total)
{
    int idx = blockIdx.x * blockDim.x + threadIdx.x;
    if (idx >= total) return;
    float* x = (which == 1) ? g_q : g_k;
    int i = idx & 63;
    int h = (idx >> 6) % nheads;
    int m = idx / (64 * nheads);
    int s = m & (S_ - 1);
    float c  = g_cos[s * 64 + i];
    float sn = g_sin[s * 64 + i];
    float* p = x + ((size_t)m * nheads + h) * HD_;
    float x1 = p[i], x2 = p[i + 64];
    p[i]      = x1 * c - x2 * sn;
    p[i + 64] = x2 * c + x1 * sn;
}

// ---------------- fp32 causal flash attention --------------------------------
#define BR 64
#define BC 64
#define QSTR 132
#define PSTR 68
#define FLASH_SMEM ((2*BR*QSTR + BR*PSTR) * (int)sizeof(float))

__global__ __launch_bounds__(256, 2) void flash_attn()
{
    extern __shared__ float sm[];
    float* Qs = sm;
    float* Ks = sm + BR * QSTR;
    float* Ps = sm + 2 * BR * QSTR;

    const int tid = threadIdx.x;
    const int tx = tid & 15, ty = tid >> 4;
    const int qb = blockIdx.x, h = blockIdx.y, b = blockIdx.z;
    const int hk = h >> 2;
    const int q0 = qb * BR;

    const float* Qg = g_q + (((size_t)b * S_ + q0) * NH_ + h) * HD_;
#pragma unroll 4
    for (int idx = tid; idx < BR * 32; idx += 256) {
        int r = idx >> 5, c4 = idx & 31;
        *(float4*)&Qs[r * QSTR + c4 * 4] =
            *(const float4*)(Qg + (size_t)r * (NH_ * HD_) + c4 * 4);
    }

    float m_i[4], l_i[4], acc[4][8];
#pragma unroll
    for (int i = 0; i < 4; i++) {
        m_i[i] = -INFINITY; l_i[i] = 0.f;
#pragma unroll
        for (int c = 0; c < 8; c++) acc[i][c] = 0.f;
    }

    const float scale = 0.08838834764831845f;

    for (int jb = 0; jb <= qb; jb++) {
        const int j0 = jb * BC;

        const float* Kg = g_k + (((size_t)b * S_ + j0) * NKV_ + hk) * HD_;
#pragma unroll 4
        for (int idx = tid; idx < BC * 32; idx += 256) {
            int r = idx >> 5, c4 = idx & 31;
            *(float4*)&Ks[r * QSTR + c4 * 4] =
                *(const float4*)(Kg + (size_t)r * (NKV_ * HD_) + c4 * 4);
        }
        __syncthreads();

        float sv[4][4];
#pragma unroll
        for (int i = 0; i < 4; i++)
#pragma unroll
            for (int jj = 0; jj < 4; jj++) sv[i][jj] = 0.f;

        for (int d4 = 0; d4 < 32; d4++) {
            float4 qv[4], kvv[4];
#pragma unroll
            for (int i = 0; i < 4; i++)
                qv[i] = *(const float4*)&Qs[(ty * 4 + i) * QSTR + d4 * 4];
#pragma unroll
            for (int jj = 0; jj < 4; jj++)
                kvv[jj] = *(const float4*)&Ks[(tx + 16 * jj) * QSTR + d4 * 4];
#pragma unroll
            for (int i = 0; i < 4; i++)
#pragma unroll
                for (int jj = 0; jj < 4; jj++) {
                    sv[i][jj] = fmaf(qv[i].x, kvv[jj].x, sv[i][jj]);
                    sv[i][jj] = fmaf(qv[i].y, kvv[jj].y, sv[i][jj]);
                    sv[i][jj] = fmaf(qv[i].z, kvv[jj].z, sv[i][jj]);
                    sv[i][jj] = fmaf(qv[i].w, kvv[jj].w, sv[i][jj]);
                }
        }

        const bool diag = (jb == qb);
#pragma unroll
        for (int i = 0; i < 4; i++) {
            const int row = q0 + ty * 4 + i;
            float mx = -INFINITY;
#pragma unroll
            for (int jj = 0; jj < 4; jj++) {
                float x = sv[i][jj] * scale;
                if (diag && (j0 + tx + 16 * jj) > row) x = -INFINITY;
                sv[i][jj] = x;
                mx = fmaxf(mx, x);
            }
#pragma unroll
            for (int off = 8; off; off >>= 1)
                mx = fmaxf(mx, __shfl_xor_sync(0xffffffffu, mx, off));
            float mnew = fmaxf(m_i[i], mx);
            float corr = __expf(m_i[i] - mnew);
            float rs = 0.f;
#pragma unroll
            for (int jj = 0; jj < 4; jj++) {
                float p = __expf(sv[i][jj] - mnew);
                sv[i][jj] = p;
                rs += p;
            }
#pragma unroll
            for (int off = 8; off; off >>= 1)
                rs += __shfl_xor_sync(0xffffffffu, rs, off);
            l_i[i] = l_i[i] * corr + rs;
            m_i[i] = mnew;
#pragma unroll
            for (int c = 0; c < 8; c++) acc[i][c] *= corr;
#pragma unroll
            for (int jj = 0; jj < 4; jj++)
                Ps[(ty * 4 + i) * PSTR + tx + 16 * jj] = sv[i][jj];
        }
        __syncthreads();

        const float* Vg = g_v + (((size_t)b * S_ + j0) * NKV_ + hk) * HD_;
#pragma unroll 4
        for (int idx = tid; idx < BC * 32; idx += 256) {
            int r = idx >> 5, c4 = idx & 31;
            *(float4*)&Ks[r * QSTR + c4 * 4] =
                *(const float4*)(Vg + (size_t)r * (NKV_ * HD_) + c4 * 4);
        }
        __syncthreads();

#pragma unroll 4
        for (int j = 0; j < BC; j++) {
            float pv[4];
#pragma unroll
            for (int i = 0; i < 4; i++) pv[i] = Ps[(ty * 4 + i) * PSTR + j];
            float4 v0 = *(const float4*)&Ks[j * QSTR + tx * 8];
            float4 v1 = *(const float4*)&Ks[j * QSTR + tx * 8 + 4];
            float vv[8] = {v0.x, v0.y, v0.z, v0.w, v1.x, v1.y, v1.z, v1.w};
#pragma unroll
            for (int i = 0; i < 4; i++)
#pragma unroll
                for (int c = 0; c < 8; c++)
                    acc[i][c] = fmaf(pv[i], vv[c], acc[i][c]);
        }
        __syncthreads();
    }

#pragma unroll
    for (int i = 0; i < 4; i++) {
        float inv = 1.0f / l_i[i];
        float* Og = g_ao + (((size_t)b * S_ + q0 + ty * 4 + i) * NH_ + h) * HD_ + tx * 8;
        float4 o0 = make_float4(acc[i][0] * inv, acc[i][1] * inv, acc[i][2] * inv, acc[i][3] * inv);
        float4 o1 = make_float4(acc[i][4] * inv, acc[i][5] * inv, acc[i][6] * inv, acc[i][7] * inv);
        *(float4*)Og = o0;
        *(float4*)(Og + 4) = o1;
    }
}

// ---------------- launch ----------------------------------------------------
extern "C" void kernel_launch(void* const* d_in, const int* in_sizes, int n_in,
                              void* d_out, int out_size)
{
    (void)in_sizes; (void)n_in; (void)out_size;
    const float* hs = (const float*)d_in[0];
    const float* Wq = (const float*)d_in[1];
    const float* Wk = (const float*)d_in[2];
    const float* Wv = (const float*)d_in[3];
    const float* Wo = (const float*)d_in[4];
    float* out = (float*)d_out;

    cudaFuncSetAttribute(tc_gemm, cudaFuncAttributeMaxDynamicSharedMemorySize, GEMM_SMEM);
    cudaFuncSetAttribute(flash_attn, cudaFuncAttributeMaxDynamicSharedMemorySize, FLASH_SMEM);

    rope_table_kernel<<<(S_ * 64 + 255) / 256, 256>>>();

    // bf16 hi/lo splits
    {
        int n;
        n = M_ * H_;      split_bf16<<<n / 4 / 256, 256>>>(hs, 0, n);
        n = 2048 * H_;    split_bf16<<<n / 4 / 256, 256>>>(Wq, 1, n);
        n = 512 * H_;     split_bf16<<<n / 4 / 256, 256>>>(Wk, 2, n);
        n = 512 * H_;     split_bf16<<<n / 4 / 256, 256>>>(Wv, 3, n);
        n = 2048 * H_;    split_bf16<<<n / 4 / 256, 256>>>(Wo, 4, n);
    }

    // QKV projections (mma.sync bf16x3)
    tc_gemm<<<dim3(16, 32), 256, GEMM_SMEM>>>(0, nullptr);
    tc_gemm<<<dim3(4, 32),  256, GEMM_SMEM>>>(1, nullptr);
    tc_gemm<<<dim3(4, 32),  256, GEMM_SMEM>>>(2, nullptr);

    // RoPE
    int tq = M_ * NH_ * 64;
    rope_apply<<<(tq + 255) / 256, 256>>>(1, NH_, tq);
    int tk = M_ * NKV_ * 64;
    rope_apply<<<(tk + 255) / 256, 256>>>(2, NKV_, tk);

    // Flash attention (fp32 SIMT)
    flash_attn<<<dim3(S_ / BR, NH_, B_), 256, FLASH_SMEM>>>();

    // Output projection
    {
        int n = M_ * 2048;
        split_bf16<<<n / 4 / 256, 256>>>(nullptr, 5, n);
    }
    tc_gemm<<<dim3(16, 32), 256, GEMM_SMEM>>>(3, out);
}